// round 2
// baseline (speedup 1.0000x reference)
#include <cuda_runtime.h>
#include <cstdint>

#define N_NODES 100000
#define N_EDGES 6400000
#define MIN_DIST 5.0f

// Scratch accumulators (no device allocation allowed -> __device__ globals).
// g_acc[i] = {coll_sum.x, coll_sum.y, mean_sum.x, mean_sum.y}
__device__ __align__(16) float4 g_acc[N_NODES];
__device__ float g_cnt[N_NODES];

__global__ void zero_kernel() {
    int i = blockIdx.x * blockDim.x + threadIdx.x;
    if (i < N_NODES) {
        g_acc[i] = make_float4(0.f, 0.f, 0.f, 0.f);
        g_cnt[i] = 0.f;
    }
}

__global__ void edge_kernel(const float2* __restrict__ pos,
                            const float2* __restrict__ vel,
                            const int* __restrict__ src,
                            const int* __restrict__ dst) {
    int e = blockIdx.x * blockDim.x + threadIdx.x;
    if (e >= N_EDGES) return;

    int s = __ldg(&src[e]);
    int d = __ldg(&dst[e]);

    float2 ps = __ldg(&pos[s]);
    float2 pd = __ldg(&pos[d]);
    float2 vs = __ldg(&vel[s]);
    float2 vd = __ldg(&vel[d]);

    float dx = ps.x - pd.x;
    float dy = ps.y - pd.y;
    float n2 = dx * dx + dy * dy;
    float norm = sqrtf(n2);

    float cx = 0.f, cy = 0.f;
    if (norm > 0.f) {
        // sigmoid(-10*(norm-5)) = 1/(1+exp(10*(norm-5)))
        float sig = 1.f / (1.f + __expf(10.f * (norm - MIN_DIST)));
        float k = -sig / norm;
        cx = k * dx;
        cy = k * dy;
    }

    float mx = dx * (1.f / 30.f) + (vs.x - vd.x);
    float my = dy * (1.f / 30.f) + (vs.y - vd.y);

    float4* accp = &g_acc[d];
    asm volatile("red.global.add.v4.f32 [%0], {%1, %2, %3, %4};"
                 :: "l"(accp), "f"(cx), "f"(cy), "f"(mx), "f"(my)
                 : "memory");
    float* cntp = &g_cnt[d];
    asm volatile("red.global.add.f32 [%0], %1;"
                 :: "l"(cntp), "f"(1.0f)
                 : "memory");
}

__global__ void finalize_kernel(float2* __restrict__ out) {
    int i = blockIdx.x * blockDim.x + threadIdx.x;
    if (i < N_NODES) {
        float4 a = g_acc[i];
        float c = fmaxf(g_cnt[i], 1.0f);
        float inv = 1.0f / c;
        float2 o;
        o.x = a.x * 5.0f + a.z * inv;
        o.y = a.y * 5.0f + a.w * inv;
        out[i] = o;
    }
}

extern "C" void kernel_launch(void* const* d_in, const int* in_sizes, int n_in,
                              void* d_out, int out_size) {
    const float2* pos = (const float2*)d_in[0];
    const float2* vel = (const float2*)d_in[1];
    const int* edge = (const int*)d_in[2];
    const int* src = edge;
    const int* dst = edge + N_EDGES;
    float2* out = (float2*)d_out;

    {
        int threads = 256;
        int blocks = (N_NODES + threads - 1) / threads;
        zero_kernel<<<blocks, threads>>>();
    }
    {
        int threads = 256;
        int blocks = (N_EDGES + threads - 1) / threads;
        edge_kernel<<<blocks, threads>>>(pos, vel, src, dst);
    }
    {
        int threads = 256;
        int blocks = (N_NODES + threads - 1) / threads;
        finalize_kernel<<<blocks, threads>>>(out);
    }
}

// round 5
// speedup vs baseline: 1.3559x; 1.3559x over previous
#include <cuda_runtime.h>
#include <cstdint>

#define N_NODES 100000
#define N_EDGES 6400000
#define MIN_DIST 5.0f

// Per-node 32B accumulator: one L2 sector holds vector acc + count.
struct __align__(32) Acc {
    float4 a;      // {coll.x, coll.y, mean.x, mean.y}
    float  cnt;
    float  pad[3];
};

__device__ Acc    g_acc[N_NODES];
__device__ float4 g_h[N_NODES];     // {pos.x, pos.y, vel.x, vel.y}

// Fused prep: zero accumulators + build packed h array.
__global__ void prep_kernel(const float2* __restrict__ pos,
                            const float2* __restrict__ vel) {
    int i = blockIdx.x * blockDim.x + threadIdx.x;
    if (i < N_NODES) {
        g_acc[i].a = make_float4(0.f, 0.f, 0.f, 0.f);
        g_acc[i].cnt = 0.f;
        float2 p = pos[i];
        float2 v = vel[i];
        g_h[i] = make_float4(p.x, p.y, v.x, v.y);
    }
}

__global__ void __launch_bounds__(256) edge_kernel(const int4* __restrict__ src4,
                                                   const int4* __restrict__ dst4) {
    int t = blockIdx.x * blockDim.x + threadIdx.x;
    if (t >= N_EDGES / 4) return;

    int4 s4 = __ldg(&src4[t]);
    int4 d4 = __ldg(&dst4[t]);

    int s[4] = {s4.x, s4.y, s4.z, s4.w};
    int d[4] = {d4.x, d4.y, d4.z, d4.w};

    // Batch all 8 gathers up front for MLP.
    float4 hs[4], hd[4];
#pragma unroll
    for (int k = 0; k < 4; k++) hs[k] = g_h[s[k]];
#pragma unroll
    for (int k = 0; k < 4; k++) hd[k] = g_h[d[k]];

#pragma unroll
    for (int k = 0; k < 4; k++) {
        float dx = hs[k].x - hd[k].x;
        float dy = hs[k].y - hd[k].y;
        float n2 = dx * dx + dy * dy;

        // rn = 1/norm (0 if norm==0, handles self-edges branchlessly)
        float rn = (n2 > 0.f) ? rsqrtf(n2) : 0.f;
        float norm = n2 * rn;

        // sigmoid(-10*(norm-5)) = 1/(1+exp(10*(norm-5)))
        float sig = 1.f / (1.f + __expf(10.f * (norm - MIN_DIST)));
        float kk = -sig * rn;
        float cx = kk * dx;
        float cy = kk * dy;

        float mx = dx * (1.f / 30.f) + (hs[k].z - hd[k].z);
        float my = dy * (1.f / 30.f) + (hs[k].w - hd[k].w);

        Acc* accp = &g_acc[d[k]];
        asm volatile("red.global.add.v4.f32 [%0], {%1, %2, %3, %4};"
                     :: "l"(&accp->a), "f"(cx), "f"(cy), "f"(mx), "f"(my)
                     : "memory");
        asm volatile("red.global.add.f32 [%0], %1;"
                     :: "l"(&accp->cnt), "f"(1.0f)
                     : "memory");
    }
}

__global__ void finalize_kernel(float2* __restrict__ out) {
    int i = blockIdx.x * blockDim.x + threadIdx.x;
    if (i < N_NODES) {
        float4 a = g_acc[i].a;
        float c = fmaxf(g_acc[i].cnt, 1.0f);
        float inv = 1.0f / c;
        float2 o;
        o.x = a.x * 5.0f + a.z * inv;
        o.y = a.y * 5.0f + a.w * inv;
        out[i] = o;
    }
}

extern "C" void kernel_launch(void* const* d_in, const int* in_sizes, int n_in,
                              void* d_out, int out_size) {
    const float2* pos = (const float2*)d_in[0];
    const float2* vel = (const float2*)d_in[1];
    const int* edge = (const int*)d_in[2];
    const int4* src4 = (const int4*)edge;
    const int4* dst4 = (const int4*)(edge + N_EDGES);
    float2* out = (float2*)d_out;

    {
        int threads = 256;
        int blocks = (N_NODES + threads - 1) / threads;
        prep_kernel<<<blocks, threads>>>(pos, vel);
    }
    {
        int threads = 256;
        int nthreads = N_EDGES / 4;
        int blocks = (nthreads + threads - 1) / threads;
        edge_kernel<<<blocks, threads>>>(src4, dst4);
    }
    {
        int threads = 256;
        int blocks = (N_NODES + threads - 1) / threads;
        finalize_kernel<<<blocks, threads>>>(out);
    }
}

// round 6
// speedup vs baseline: 2.8540x; 2.1049x over previous
#include <cuda_runtime.h>
#include <cstdint>

#define N_NODES 100000
#define N_EDGES 6400000
#define MIN_DIST 5.0f
#define CNT_OFFSET 512.0f

// Per-node 16B accumulator: {cx_sum + 512*cnt, cy_sum, mx_sum, my_sum}
// |sum(cx)| <= cnt <= ~120 < 256, so cnt = rint(x/512) is exact.
__device__ __align__(16) float4 g_acc[N_NODES];
__device__ float4 g_h[N_NODES];     // {pos.x, pos.y, vel.x, vel.y}

// Fused prep: zero accumulators + build packed h array.
__global__ void prep_kernel(const float2* __restrict__ pos,
                            const float2* __restrict__ vel) {
    int i = blockIdx.x * blockDim.x + threadIdx.x;
    if (i < N_NODES) {
        g_acc[i] = make_float4(0.f, 0.f, 0.f, 0.f);
        float2 p = pos[i];
        float2 v = vel[i];
        g_h[i] = make_float4(p.x, p.y, v.x, v.y);
    }
}

__global__ void __launch_bounds__(256) edge_kernel(const int4* __restrict__ src4,
                                                   const int4* __restrict__ dst4) {
    int t = blockIdx.x * blockDim.x + threadIdx.x;
    if (t >= N_EDGES / 4) return;

    int4 s4 = __ldg(&src4[t]);
    int4 d4 = __ldg(&dst4[t]);

    int s[4] = {s4.x, s4.y, s4.z, s4.w};
    int d[4] = {d4.x, d4.y, d4.z, d4.w};

    // Batch all 8 gathers up front for MLP.
    float4 hs[4], hd[4];
#pragma unroll
    for (int k = 0; k < 4; k++) hs[k] = g_h[s[k]];
#pragma unroll
    for (int k = 0; k < 4; k++) hd[k] = g_h[d[k]];

#pragma unroll
    for (int k = 0; k < 4; k++) {
        float dx = hs[k].x - hd[k].x;
        float dy = hs[k].y - hd[k].y;
        float n2 = dx * dx + dy * dy;

        // rn = 1/norm (0 if norm==0, handles self-edges branchlessly)
        float rn = (n2 > 0.f) ? rsqrtf(n2) : 0.f;
        float norm = n2 * rn;

        // sigmoid(-10*(norm-5)) = 1/(1+exp(10*(norm-5)))
        float sig = 1.f / (1.f + __expf(10.f * (norm - MIN_DIST)));
        float kk = -sig * rn;
        float cx = kk * dx;
        float cy = kk * dy;

        float mx = dx * (1.f / 30.f) + (hs[k].z - hd[k].z);
        float my = dy * (1.f / 30.f) + (hs[k].w - hd[k].w);

        // Single 16B reduction per edge; count encoded as +512 in lane x.
        asm volatile("red.global.add.v4.f32 [%0], {%1, %2, %3, %4};"
                     :: "l"(&g_acc[d[k]]),
                        "f"(cx + CNT_OFFSET), "f"(cy), "f"(mx), "f"(my)
                     : "memory");
    }
}

__global__ void finalize_kernel(float2* __restrict__ out) {
    int i = blockIdx.x * blockDim.x + threadIdx.x;
    if (i < N_NODES) {
        float4 a = g_acc[i];
        float cnt = rintf(a.x * (1.0f / CNT_OFFSET));
        float sum_cx = a.x - cnt * CNT_OFFSET;
        float inv = 1.0f / fmaxf(cnt, 1.0f);
        float2 o;
        o.x = sum_cx * 5.0f + a.z * inv;
        o.y = a.y    * 5.0f + a.w * inv;
        out[i] = o;
    }
}

extern "C" void kernel_launch(void* const* d_in, const int* in_sizes, int n_in,
                              void* d_out, int out_size) {
    const float2* pos = (const float2*)d_in[0];
    const float2* vel = (const float2*)d_in[1];
    const int* edge = (const int*)d_in[2];
    const int4* src4 = (const int4*)edge;
    const int4* dst4 = (const int4*)(edge + N_EDGES);
    float2* out = (float2*)d_out;

    {
        int threads = 256;
        int blocks = (N_NODES + threads - 1) / threads;
        prep_kernel<<<blocks, threads>>>(pos, vel);
    }
    {
        int threads = 256;
        int nthreads = N_EDGES / 4;
        int blocks = (nthreads + threads - 1) / threads;
        edge_kernel<<<blocks, threads>>>(src4, dst4);
    }
    {
        int threads = 256;
        int blocks = (N_NODES + threads - 1) / threads;
        finalize_kernel<<<blocks, threads>>>(out);
    }
}